// round 4
// baseline (speedup 1.0000x reference)
#include <cuda_runtime.h>
#include <cuda_bf16.h>

// Embedding gather: out[token, :] = table[ids[token], :]
// ids: [32*8192] int32, table: [256,256] f32, out: [32*8192, 256] f32.
//
// Warp-per-token layout: each thread moves 32 B (2 consecutive float4) per
// item, so one warp covers exactly one 1 KB token row per item. The ids load
// is warp-uniform (single broadcast load), table loads are 2 LDG.128 per
// item, and ITEMS=4 gives 8 independent loads per thread with low address
// register pressure (so ptxas keeps them in flight instead of serializing).
// Streaming .cs stores keep the 256 KB table resident in L2.

static constexpr int       TOKENS      = 32 * 8192;            // 262144
static constexpr int       EMBED       = 256;
static constexpr int       VEC_PER_ROW = EMBED / 4;            // 64 float4 per row
static constexpr int       ITEMS       = 4;                    // tokens per warp

__global__ __launch_bounds__(256)
void embed_gather_kernel(const int* __restrict__ ids,
                         const float4* __restrict__ table4,
                         float4* __restrict__ out4)
{
    // Global warp id; each warp handles ITEMS tokens, strided by total warps.
    const int warps_total = TOKENS / ITEMS;                    // 65536 warps
    const int lane        = threadIdx.x & 31;
    const int gwarp       = (blockIdx.x * (blockDim.x >> 5)) + (threadIdx.x >> 5);

    int    tok[ITEMS];
    float4 v0[ITEMS], v1[ITEMS];
    int    token_idx[ITEMS];

    // Phase 1: warp-uniform index loads (independent, broadcast).
    #pragma unroll
    for (int k = 0; k < ITEMS; k++) {
        token_idx[k] = gwarp + k * warps_total;
        tok[k]       = __ldg(&ids[token_idx[k]]);
    }

    // Phase 2: 8 independent table loads (2 per token, L1/L2 hits).
    #pragma unroll
    for (int k = 0; k < ITEMS; k++) {
        const float4* row = &table4[(long long)tok[k] * VEC_PER_ROW + lane * 2];
        v0[k] = __ldg(&row[0]);
        v1[k] = __ldg(&row[1]);
    }

    // Phase 3: streaming stores, 1 KB contiguous per warp per item.
    #pragma unroll
    for (int k = 0; k < ITEMS; k++) {
        float4* dst = &out4[(long long)token_idx[k] * VEC_PER_ROW + lane * 2];
        __stcs(&dst[0], v0[k]);
        __stcs(&dst[1], v1[k]);
    }
}

extern "C" void kernel_launch(void* const* d_in, const int* in_sizes, int n_in,
                              void* d_out, int out_size)
{
    const int*   ids   = (const int*)d_in[0];    // [32, 8192] int32
    const float* table = (const float*)d_in[1];  // [256, 256] f32
    float*       out   = (float*)d_out;          // [32, 8192, 256] f32

    const int threads        = 256;
    const int warps_per_blk  = threads / 32;                     // 8
    const int warps_total    = TOKENS / ITEMS;                   // 65536
    const int blocks         = warps_total / warps_per_blk;      // 8192

    embed_gather_kernel<<<blocks, threads>>>(
        ids, (const float4*)table, (float4*)out);
}

// round 5
// speedup vs baseline: 1.7227x; 1.7227x over previous
#include <cuda_runtime.h>
#include <cuda_bf16.h>

// Embedding gather: out[token, :] = table[ids[token], :]
// ids: [32*8192] int32, table: [256,256] f32, out: [32*8192, 256] f32.
//
// R2 access pattern (lane-contiguous float4 -> 4 L1 lines per warp
// instruction, the proven-fast shape) + ITEMS=8 independent chains, with
// __launch_bounds__(256, 2) to raise the ptxas register budget so the 8
// gather loads actually stay concurrently in flight in SASS (R3 showed the
// default budget collapses them to MLP~1). Streaming .cs stores keep the
// 256 KB table resident in L2.

static constexpr int       TOKENS       = 32 * 8192;          // 262144
static constexpr int       EMBED        = 256;
static constexpr int       VEC_PER_ROW  = EMBED / 4;          // 64 float4 per row
static constexpr long long TOTAL_VEC4   = (long long)TOKENS * VEC_PER_ROW; // 16,777,216
static constexpr int       ITEMS        = 8;                  // chains per thread

__global__ __launch_bounds__(256, 2)
void embed_gather_kernel(const int* __restrict__ ids,
                         const float4* __restrict__ table4,
                         float4* __restrict__ out4)
{
    const long long NT   = TOTAL_VEC4 / ITEMS;                 // threads total
    long long       gtid = (long long)blockIdx.x * blockDim.x + threadIdx.x;

    long long g[ITEMS];
    int       tok[ITEMS];
    float4    v[ITEMS];

    // Batch the index loads (independent; near-uniform within a warp).
    #pragma unroll
    for (int k = 0; k < ITEMS; k++) {
        g[k]   = gtid + (long long)k * NT;
        tok[k] = __ldg(&ids[g[k] >> 6]);
    }

    // Batch the table loads (8 independent LDG.128, L1/L2 hits).
    #pragma unroll
    for (int k = 0; k < ITEMS; k++) {
        v[k] = __ldg(&table4[(long long)tok[k] * VEC_PER_ROW + (g[k] & 63)]);
    }

    // Streaming stores: lane-contiguous 16B -> 512B per warp instruction.
    #pragma unroll
    for (int k = 0; k < ITEMS; k++) {
        __stcs(&out4[g[k]], v[k]);
    }
}

extern "C" void kernel_launch(void* const* d_in, const int* in_sizes, int n_in,
                              void* d_out, int out_size)
{
    const int*   ids   = (const int*)d_in[0];    // [32, 8192] int32
    const float* table = (const float*)d_in[1];  // [256, 256] f32
    float*       out   = (float*)d_out;          // [32, 8192, 256] f32

    const int threads = 256;
    const int blocks  = (int)(TOTAL_VEC4 / ITEMS / threads);   // 8192

    embed_gather_kernel<<<blocks, threads>>>(
        ids, (const float4*)table, (float4*)out);
}

// round 6
// speedup vs baseline: 1.7496x; 1.0156x over previous
#include <cuda_runtime.h>
#include <cuda_bf16.h>

// Embedding gather: out[token, :] = table[ids[token], :]
// ids: [32*8192] int32, table: [256,256] f32, out: [32*8192, 256] f32.
//
// Store-bandwidth-bound (268 MB written). Proven-fast shape from R2:
// lane-contiguous float4 (512B per warp store instruction), 4 independent
// gather->store chains per thread, streaming .cs stores. R6 change: each
// block's 4 items are CONTIGUOUS (block owns one 16 KB output chunk,
// k-iterations step 4 KB within it) to maximize DRAM row-buffer locality
// on the write drain instead of 8 scattered streams per thread.

static constexpr int       TOKENS       = 32 * 8192;          // 262144
static constexpr int       EMBED        = 256;
static constexpr int       VEC_PER_ROW  = EMBED / 4;          // 64 float4 per row
static constexpr long long TOTAL_VEC4   = (long long)TOKENS * VEC_PER_ROW; // 16,777,216
static constexpr int       ITEMS        = 4;                  // chains per thread
static constexpr int       THREADS      = 256;

__global__ __launch_bounds__(THREADS)
void embed_gather_kernel(const int* __restrict__ ids,
                         const float4* __restrict__ table4,
                         float4* __restrict__ out4)
{
    // Block-contiguous: block b owns float4 range
    // [b*ITEMS*THREADS, (b+1)*ITEMS*THREADS), k steps by THREADS (4 KB).
    const long long base = (long long)blockIdx.x * (ITEMS * THREADS) + threadIdx.x;

    long long g[ITEMS];
    int       tok[ITEMS];
    float4    v[ITEMS];

    // Batched index loads (warp-uniform -> broadcast L1 hits).
    #pragma unroll
    for (int k = 0; k < ITEMS; k++) {
        g[k]   = base + k * THREADS;
        tok[k] = __ldg(&ids[g[k] >> 6]);
    }

    // Batched table loads (independent LDG.128; table resident in L1/L2).
    #pragma unroll
    for (int k = 0; k < ITEMS; k++) {
        v[k] = __ldg(&table4[(long long)tok[k] * VEC_PER_ROW + (g[k] & 63)]);
    }

    // Streaming stores: contiguous 4 KB per block per k-step.
    #pragma unroll
    for (int k = 0; k < ITEMS; k++) {
        __stcs(&out4[g[k]], v[k]);
    }
}

extern "C" void kernel_launch(void* const* d_in, const int* in_sizes, int n_in,
                              void* d_out, int out_size)
{
    const int*   ids   = (const int*)d_in[0];    // [32, 8192] int32
    const float* table = (const float*)d_in[1];  // [256, 256] f32
    float*       out   = (float*)d_out;          // [32, 8192, 256] f32

    const int blocks = (int)(TOTAL_VEC4 / (ITEMS * THREADS));  // 16384

    embed_gather_kernel<<<blocks, THREADS>>>(
        ids, (const float4*)table, (float4*)out);
}